// round 7
// baseline (speedup 1.0000x reference)
#include <cuda_runtime.h>
#include <cuda_fp16.h>

// Signature-kernel MMD. WPC=1: 2080 single-warp CTAs, 8.6KB smem each ->
// 26 CTAs/SM capacity -> ALL tasks resident in wave 1 (no tail). PDE loop
// unrolled x2 with paired half2 loads (3 LDS.U32 per 4 diagonals) + carried
// operands (a0A, a2, sh2). fp16 eps table (eps = 0.25*inc). O region odd-
// aligned, E region even-aligned so every paired PDE read is 4B-aligned.
// Masking-free Goursat wavefront; last-block deterministic reduction.

#define BSZ 32
#define LEN 64
#define NTRI ((BSZ*(BSZ+1))/2)     // 528
#define NTASKS (2*NTRI + BSZ*BSZ)  // 2080

#define RSH 68                     // row stride in halves
#define OOFF 9                     // Ob = warpbase + 9 (odd)
#define OSZH (31*RSH)              // 2108
#define EOFF (OOFF + OSZH + 1)     // 2118 (even) -> Eb even-aligned
#define ESZH (32*RSH)              // 2176
#define WHALVES 4296               // 8592 B, 16B multiple

__device__ float g_partial[NTASKS];
__device__ unsigned int g_count;   // zero-init; reducer re-arms

__global__ void __launch_bounds__(32)
sig_kernel(const float* __restrict__ x, const float* __restrict__ y,
           float* __restrict__ out)
{
    extern __shared__ __align__(16) char smem[];
    const int lane = threadIdx.x & 31;
    const int task = blockIdx.x;

    __half* warpbase = reinterpret_cast<__half*>(smem);
    __half* Ob = warpbase + OOFF;      // odd address parity
    __half* Eb = warpbase + EOFF;      // even address parity

    // Zero whole region: all stray PDE reads must return finite values.
    {
        uint4* z = reinterpret_cast<uint4*>(warpbase);
        #pragma unroll
        for (int i = lane; i < (WHALVES*2)/16; i += 32)
            z[i] = make_uint4(0u, 0u, 0u, 0u);
    }

    // ---- decode task -> pair pointers + weight ----
    const float *pa, *pb;
    float weight;
    {
        int t = task;
        if (t < 2*NTRI) {
            const float* base = (t < NTRI) ? x : y;
            if (t >= NTRI) t -= NTRI;
            int a = 0;
            while (t >= (BSZ - a)) { t -= (BSZ - a); ++a; }
            int b = a + t;
            pa = base + a*(LEN*4);
            pb = base + b*(LEN*4);
            weight = (a == b ? 1.0f : 2.0f) * (1.0f/1024.0f);
        } else {
            t -= 2*NTRI;
            pa = x + (t >> 5)*(LEN*4);
            pb = y + (t & 31)*(LEN*4);
            weight = -2.0f/1024.0f;
        }
    }

    // ---- streaming RBF gram + second differences -> eps = 0.25*inc (fp16) ----
    const int j0 = lane << 1;
    const float4 b0 = __ldg(reinterpret_cast<const float4*>(pb + 4*j0));
    const float4 b1 = __ldg(reinterpret_cast<const float4*>(pb + 4*j0 + 4));

    float g0p, g1p;
    {
        float4 a = __ldg(reinterpret_cast<const float4*>(pa));
        float d0x=a.x-b0.x, d0y=a.y-b0.y, d0z=a.z-b0.z, d0w=a.w-b0.w;
        float d1x=a.x-b1.x, d1y=a.y-b1.y, d1z=a.z-b1.z, d1w=a.w-b1.w;
        g0p = __expf(-0.5f*(d0x*d0x + d0y*d0y + d0z*d0z + d0w*d0w));
        g1p = __expf(-0.5f*(d1x*d1x + d1y*d1y + d1z*d1z + d1w*d1w));
    }
    #pragma unroll 4
    for (int u = 1; u < LEN; ++u) {
        float4 a = __ldg(reinterpret_cast<const float4*>(pa + 4*u));
        float d0x=a.x-b0.x, d0y=a.y-b0.y, d0z=a.z-b0.z, d0w=a.w-b0.w;
        float d1x=a.x-b1.x, d1y=a.y-b1.y, d1z=a.z-b1.z, d1w=a.w-b1.w;
        float g0 = __expf(-0.5f*(d0x*d0x + d0y*d0y + d0z*d0z + d0w*d0w));
        float g1 = __expf(-0.5f*(d1x*d1x + d1y*d1y + d1z*d1z + d1w*d1w));
        float t0 = g0 - g0p;
        float t1 = g1 - g1p;
        float tn = __shfl_down_sync(0xffffffffu, t0, 1);
        float e0 = 0.25f * (t1 - t0);
        float e1 = 0.25f * (tn - t1);
        int v = u - 1;
        if (v & 1) {                 // odd row -> O region (odd-aligned): 2x u16
            __half* row = Ob + (v >> 1) * RSH;
            row[j0]     = __float2half_rn(e0);
            row[j0 + 1] = __float2half_rn(e1);
        } else {                     // even row -> E region: aligned half2
            __half* row = Eb + (v >> 1) * RSH;
            reinterpret_cast<__half2*>(row)[lane] = __floats2half2_rn(e0, e1);
        }
        g0p = g0; g1p = g1;
    }
    __syncwarp();

    // ---- Goursat PDE, antidiagonal wavefront ----
    // Lane holds cells i = 4*lane + k. Carried: a0A(m)=a0B(m-1), a2(m)=a1(m-1),
    // sh2(m)=sh1b(m-1). Unrolled x2 with half2 paired loads (all 4B-aligned).
    const int L = lane;
    const bool isL0 = (L == 0);
    const __half* p0 = Ob + ((L == 0) ? 0 : (66*L - 68));
    const __half* p1 = Eb + 66*L;
    const __half* p3 = Ob + 66*L - 1;

    float A0 = isL0 ? 1.f : 0.f, A1 = 0.f, A2 = 0.f, A3 = 0.f;   // diag 0
    float B0 = A0, B1 = A0, B2 = 0.f, B3 = 0.f;                  // diag 1

    float a0A = __half2float(p0[0]) - 1.0f;
    float a2  = __half2float(p1[-1]) - 1.0f;    // p2[0] == p1[-1]
    float sh2 = 0.0f;

#define PDE_BODY(A0_,A1_,A2_,A3_,B0_,B1_,B2_,B3_, a0B_, a1_, a3_)              \
    {                                                                          \
        float sh1 = __shfl_up_sync(0xffffffffu, B3_, 1);                       \
        float v0 = fmaf(sh2, a0A, sh1) + B0_;  if (isL0) v0 = 1.f;             \
        float v1 = fmaf(A0_, (a1_), B0_) + B1_;                                \
        float v2 = fmaf(A1_, a2,   B1_) + B2_;                                 \
        float v3 = fmaf(A2_, (a3_), B2_) + B3_;                                \
        float sh1b = __shfl_up_sync(0xffffffffu, v3, 1);                       \
        float w0 = fmaf(sh1, (a0B_), sh1b) + v0; if (isL0) w0 = 1.f;           \
        float w1 = fmaf(B0_, (a1_), v0) + v1;                                  \
        float w2 = fmaf(B1_, (a1_), v1) + v2;                                  \
        float w3 = fmaf(B2_, (a3_), v2) + v3;                                  \
        A0_ = v0; A1_ = v1; A2_ = v2; A3_ = v3;                                \
        B0_ = w0; B1_ = w1; B2_ = w2; B3_ = w3;                                \
        a0A = (a0B_); a2 = (a1_); sh2 = sh1b;                                  \
    }

    #pragma unroll 2
    for (int m = 0; m < 124; m += 2) {
        float2 P0 = __half22float2(*reinterpret_cast<const __half2*>(p0 + m + 1));
        float2 P1 = __half22float2(*reinterpret_cast<const __half2*>(p1 + m));
        float2 P3 = __half22float2(*reinterpret_cast<const __half2*>(p3 + m));
        float q0a = P0.x - 1.0f, q0b = P0.y - 1.0f;
        float q1a = P1.x - 1.0f, q1b = P1.y - 1.0f;
        float q3a = P3.x - 1.0f, q3b = P3.y - 1.0f;
        PDE_BODY(A0,A1,A2,A3,B0,B1,B2,B3, q0a, q1a, q3a)   // iter m
        PDE_BODY(A0,A1,A2,A3,B0,B1,B2,B3, q0b, q1b, q3b)   // iter m+1
    }
    {   // remainder iter m=124 (scalar loads)
        float q0 = __half2float(p0[125]) - 1.0f;
        float q1 = __half2float(p1[124]) - 1.0f;
        float q3 = __half2float(p3[124]) - 1.0f;
        PDE_BODY(A0,A1,A2,A3,B0,B1,B2,B3, q0, q1, q3)
    }
#undef PDE_BODY

    // final diag 252: cell k=2 on lane 31 (i=126, j=126); inc = carried a2.
    float f2 = fmaf(A1, a2, B1) + B2;
    float res = __shfl_sync(0xffffffffu, f2, 31);
    if (lane == 0) g_partial[task] = res * weight;

    // ---- last-block deterministic reduction (single warp) ----
    __threadfence();
    __syncwarp();
    unsigned int ticket = 0;
    if (lane == 0) ticket = atomicAdd(&g_count, 1u);
    ticket = __shfl_sync(0xffffffffu, ticket, 0);
    if (ticket == (unsigned)(gridDim.x - 1)) {
        double s = 0.0;
        for (int i = lane; i < NTASKS; i += 32)
            s += (double)__ldcg(&g_partial[i]);
        #pragma unroll
        for (int w = 16; w > 0; w >>= 1)
            s += __shfl_down_sync(0xffffffffu, s, w);
        if (lane == 0) {
            out[0] = (float)s;
            g_count = 0;                 // re-arm for next graph replay
        }
    }
}

extern "C" void kernel_launch(void* const* d_in, const int* in_sizes, int n_in,
                              void* d_out, int out_size)
{
    const float* x = (const float*)d_in[0];
    const float* y = (const float*)d_in[1];
    (void)in_sizes; (void)n_in; (void)out_size;

    cudaFuncSetAttribute(sig_kernel,
                         cudaFuncAttributePreferredSharedMemoryCarveout, 100);

    const size_t shmem = (size_t)WHALVES * sizeof(__half);  // 8592 B -> 26 CTAs/SM
    sig_kernel<<<NTASKS, 32, shmem>>>(x, y, (float*)d_out);
}

// round 8
// speedup vs baseline: 1.0813x; 1.0813x over previous
#include <cuda_runtime.h>
#include <cuda_fp16.h>

// Signature-kernel MMD. R6 base (WPC=2, 1040 CTAs, fp16 eps table, masking-free
// Goursat wavefront, carried operands) + software-pipelined PDE loop:
//   - w0 deferred one iteration (its shfl operand ages a full iteration)
//   - the 3 LDS per iteration prefetched one iteration ahead
// so every SHFL/LDS has ~30 instructions of slack at 3.5 warps/SMSP.

#define BSZ 32
#define LEN 64
#define NTRI ((BSZ*(BSZ+1))/2)     // 528
#define NTASKS (2*NTRI + BSZ*BSZ)  // 2080
#define WPC 2
#define NBLK (NTASKS / WPC)        // 1040

#define RSH 68                     // row stride in halves
#define GUARDH 8
#define OSZH (31*RSH)              // odd coarse rows 1,3,..,61
#define ESZH (32*RSH)              // even coarse rows 0,2,..,62
#define WHALVES (GUARDH + OSZH + ESZH + 4)   // 4296 halves = 8592 B / task

__device__ float g_partial[NTASKS];
__device__ unsigned int g_count;   // zero-init; reducer re-arms

__global__ void __launch_bounds__(32*WPC)
sig_kernel(const float* __restrict__ x, const float* __restrict__ y,
           float* __restrict__ out)
{
    extern __shared__ __align__(16) char smem[];
    const int lane = threadIdx.x & 31;
    const int wid  = threadIdx.x >> 5;
    const int task = blockIdx.x * WPC + wid;

    __half* warpbase = reinterpret_cast<__half*>(smem) + wid * WHALVES;
    __half* Ob = warpbase + GUARDH;
    __half* Eb = Ob + OSZH;

    // Zero own region + guard: all stray PDE reads must be finite.
    {
        uint4* z = reinterpret_cast<uint4*>(warpbase);
        #pragma unroll
        for (int i = lane; i < (WHALVES*2)/16; i += 32)
            z[i] = make_uint4(0u, 0u, 0u, 0u);
    }

    // ---- decode task -> pair pointers + weight ----
    const float *pa, *pb;
    float weight;
    {
        int t = task;
        if (t < 2*NTRI) {
            const float* base = (t < NTRI) ? x : y;
            if (t >= NTRI) t -= NTRI;
            int a = 0;
            while (t >= (BSZ - a)) { t -= (BSZ - a); ++a; }
            int b = a + t;
            pa = base + a*(LEN*4);
            pb = base + b*(LEN*4);
            weight = (a == b ? 1.0f : 2.0f) * (1.0f/1024.0f);
        } else {
            t -= 2*NTRI;
            pa = x + (t >> 5)*(LEN*4);
            pb = y + (t & 31)*(LEN*4);
            weight = -2.0f/1024.0f;
        }
    }

    // ---- streaming RBF gram + second differences -> eps = 0.25*inc (fp16) ----
    const int j0 = lane << 1;
    const float4 b0 = __ldg(reinterpret_cast<const float4*>(pb + 4*j0));
    const float4 b1 = __ldg(reinterpret_cast<const float4*>(pb + 4*j0 + 4));

    float g0p, g1p;
    {
        float4 a = __ldg(reinterpret_cast<const float4*>(pa));
        float d0x=a.x-b0.x, d0y=a.y-b0.y, d0z=a.z-b0.z, d0w=a.w-b0.w;
        float d1x=a.x-b1.x, d1y=a.y-b1.y, d1z=a.z-b1.z, d1w=a.w-b1.w;
        g0p = __expf(-0.5f*(d0x*d0x + d0y*d0y + d0z*d0z + d0w*d0w));
        g1p = __expf(-0.5f*(d1x*d1x + d1y*d1y + d1z*d1z + d1w*d1w));
    }
    #pragma unroll 4
    for (int u = 1; u < LEN; ++u) {
        float4 a = __ldg(reinterpret_cast<const float4*>(pa + 4*u));
        float d0x=a.x-b0.x, d0y=a.y-b0.y, d0z=a.z-b0.z, d0w=a.w-b0.w;
        float d1x=a.x-b1.x, d1y=a.y-b1.y, d1z=a.z-b1.z, d1w=a.w-b1.w;
        float g0 = __expf(-0.5f*(d0x*d0x + d0y*d0y + d0z*d0z + d0w*d0w));
        float g1 = __expf(-0.5f*(d1x*d1x + d1y*d1y + d1z*d1z + d1w*d1w));
        float t0 = g0 - g0p;
        float t1 = g1 - g1p;
        float tn = __shfl_down_sync(0xffffffffu, t0, 1);
        float e0 = 0.25f * (t1 - t0);
        float e1 = 0.25f * (tn - t1);
        int v = u - 1;
        __half* row = ((v & 1) ? Ob : Eb) + (v >> 1) * RSH;
        reinterpret_cast<__half2*>(row)[lane] = __floats2half2_rn(e0, e1);
        g0p = g0; g1p = g1;
    }
    __syncwarp();

    // ---- Goursat PDE, software-pipelined antidiagonal wavefront ----
    // Lane holds cells i = 4*lane + k. Iteration m handles diagonals 2m+2, 2m+3.
    // Deferred:   w0(m-1) computed at top of iter m (B0n).
    // Carried:    a0A = a0B(m-1), a2 = a1(m-1), sh2 = shfl(v3(m-1)),
    //             sh1p = shfl(B3) of previous iteration.
    // Prefetched: lm0/lm1/lm3 = this iteration's table operands (loaded last iter).
    const int L = lane;
    const bool isL0 = (L == 0);
    const __half* p0 = Ob + ((L == 0) ? 0 : (66*L - 68));
    const __half* p1 = Eb + 66*L;
    const __half* p3 = Ob + 66*L - 1;

    float A0 = isL0 ? 1.f : 0.f, A1 = 0.f, A2 = 0.f, A3 = 0.f;   // diag 0
    float B1 = A0, B2 = 0.f, B3 = 0.f;                           // diag 1 (B0 deferred)

    float a0A  = __half2float(p0[0])  - 1.0f;
    float a2   = __half2float(p1[-1]) - 1.0f;    // p2[0] == p1[-1]
    float sh2  = 0.0f;                           // shfl(A3_init) == 0
    float sh1p = 0.0f;                           // so deferred B0n(0) = A0 (= diag-1 w0)
    float lm0  = __half2float(p0[1]) - 1.0f;     // a0B(0)
    float lm1  = __half2float(p1[0]) - 1.0f;     // a1(0)
    float lm3  = __half2float(p3[0]) - 1.0f;     // a3(0)

#define PDE_STEP(PREFETCH)                                                     \
    {                                                                          \
        float B0n = fmaf(sh1p, a0A, sh2) + A0;  if (isL0) B0n = 1.f;           \
        float sh1 = __shfl_up_sync(0xffffffffu, B3, 1);                        \
        float c0 = lm0, c1 = lm1, c3 = lm3;                                    \
        PREFETCH                                                               \
        float v1 = fmaf(A0, c1, B0n) + B1;                                     \
        float v2 = fmaf(A1, a2, B1) + B2;                                      \
        float v3 = fmaf(A2, c3, B2) + B3;                                      \
        float v0 = fmaf(sh2, a0A, sh1) + B0n;  if (isL0) v0 = 1.f;             \
        float shn = __shfl_up_sync(0xffffffffu, v3, 1);                        \
        float w1 = fmaf(B0n, c1, v0) + v1;                                     \
        float w2 = fmaf(B1, c1, v1) + v2;                                      \
        float w3 = fmaf(B2, c3, v2) + v3;                                      \
        A0 = v0; A1 = v1; A2 = v2; A3 = v3;                                    \
        B1 = w1; B2 = w2; B3 = w3;                                             \
        a0A = c0; a2 = c1; sh2 = shn; sh1p = sh1;                              \
    }

    #pragma unroll 4
    for (int m = 0; m < 124; ++m) {
        PDE_STEP(
            lm0 = __half2float(p0[m+2]) - 1.0f;
            lm1 = __half2float(p1[m+1]) - 1.0f;
            lm3 = __half2float(p3[m+1]) - 1.0f;
        )
    }
    PDE_STEP( )      // m = 124, no prefetch
#undef PDE_STEP

    // final diag 252: cell k=2 on lane 31 (i=126, j=126); inc = carried a2.
    float f2 = fmaf(A1, a2, B1) + B2;
    float res = __shfl_sync(0xffffffffu, f2, 31);
    if (lane == 0) g_partial[task] = res * weight;

    // ---- last-block deterministic reduction ----
    __threadfence();
    __syncthreads();
    __shared__ unsigned int sticket;
    if (threadIdx.x == 0) sticket = atomicAdd(&g_count, 1u);
    __syncthreads();
    if (sticket == (unsigned)(gridDim.x - 1)) {
        double s = 0.0;
        for (int i = threadIdx.x; i < NTASKS; i += 32*WPC)
            s += (double)__ldcg(&g_partial[i]);
        double* ds = reinterpret_cast<double*>(smem);
        ds[threadIdx.x] = s;
        __syncthreads();
        for (int w = (32*WPC)/2; w > 0; w >>= 1) {
            if (threadIdx.x < w) ds[threadIdx.x] += ds[threadIdx.x + w];
            __syncthreads();
        }
        if (threadIdx.x == 0) {
            out[0] = (float)ds[0];
            g_count = 0;                 // re-arm for next graph replay
        }
    }
}

extern "C" void kernel_launch(void* const* d_in, const int* in_sizes, int n_in,
                              void* d_out, int out_size)
{
    const float* x = (const float*)d_in[0];
    const float* y = (const float*)d_in[1];
    (void)in_sizes; (void)n_in; (void)out_size;

    cudaFuncSetAttribute(sig_kernel,
                         cudaFuncAttributePreferredSharedMemoryCarveout, 100);

    const size_t shmem = (size_t)WPC * WHALVES * sizeof(__half);  // 17184 B
    sig_kernel<<<NBLK, 32*WPC, shmem>>>(x, y, (float*)d_out);
}